// round 15
// baseline (speedup 1.0000x reference)
#include <cuda_runtime.h>

// AttentionAggregator: out[n] = sum_k softmax_k(feats[n,k]·w) * feats[n,k],
// feats[n,k] = embed_table[neigh_idx[n,k]].
// table [VOCAB,128] f32, attn_w [128] f32, neigh_idx [N,10] (int32 or int64), out [N,128] f32.
//
// R14 = R13 resubmitted (prior round died to a container-infra failure, no
// measurement). R12 body EXACTLY (warp-per-node, online softmax in 2 groups
// of 5, butterfly reduction, 64-thread blocks, no smem, no barriers, __stcs
// out) + gathers via ld.global.nc.L1::no_allocate: table gathers have ~0.2%
// L1 hit probability, so L1 line allocation is pure fill/evict churn in the
// busiest unit (L1tex 72.8%). Hint-only change: same bytes, same paths.

#define K_NEIGH 10
#define GROUP 5
#define WARPS_PER_BLOCK 2
#define BLOCK_THREADS 64

// 16B gather load, bypassing L1 allocation.
__device__ __forceinline__ float4 ldg_nc_na(const void* p)
{
    float4 v;
    asm volatile("ld.global.nc.L1::no_allocate.v4.f32 {%0,%1,%2,%3}, [%4];"
                 : "=f"(v.x), "=f"(v.y), "=f"(v.z), "=f"(v.w)
                 : "l"(p));
    return v;
}

__global__ __launch_bounds__(BLOCK_THREADS) void attn_agg_kernel(
    const float* __restrict__ table,
    const float* __restrict__ attn_w,
    const int*   __restrict__ idx_words,   // raw index buffer viewed as int32 words
    float* __restrict__ out,
    int n_nodes,
    int vocab)
{
    int warp = threadIdx.x >> 5;
    int lane = threadIdx.x & 31;
    int node = blockIdx.x * WARPS_PER_BLOCK + warp;
    if (node >= n_nodes) return;

    // Inline dtype detection: int64 indices in [0,2^31) have all-zero odd
    // int32 words; an int32 buffer has random vocab ids there.
    int oddw = 0;
    if (lane < 16) oddw = idx_words[2 * lane + 1];
    bool is32 = __ballot_sync(0xffffffffu, oddw != 0) != 0u;

    // Load this node's K indices (lanes 0..9) -> row byte offsets.
    unsigned mybase = 0;
    if (lane < K_NEIGH) {
        int r;
        if (is32) r = idx_words[node * K_NEIGH + lane];
        else      r = (int)((const long long*)idx_words)[(size_t)node * K_NEIGH + lane];
        r = min(max(r, 0), vocab - 1);
        mybase = (unsigned)r * 512u;          // 128 floats per row
    }

    float4 w4 = ((const float4*)attn_w)[lane];

    float4 f[GROUP];
    float  s[GROUP];
    float  m, d;
    float4 acc;

    // ---- Group A: neighbors 0..4 ----
    #pragma unroll
    for (int k = 0; k < GROUP; k++) {
        unsigned off = __shfl_sync(0xffffffffu, mybase, k) + (unsigned)(lane * 16);
        f[k] = ldg_nc_na((const char*)table + off);
        s[k] = f[k].x * w4.x + f[k].y * w4.y + f[k].z * w4.z + f[k].w * w4.w;
    }
    #pragma unroll
    for (int off = 16; off > 0; off >>= 1) {
        #pragma unroll
        for (int k = 0; k < GROUP; k++)
            s[k] += __shfl_xor_sync(0xffffffffu, s[k], off);
    }
    m = s[0];
    #pragma unroll
    for (int k = 1; k < GROUP; k++) m = fmaxf(m, s[k]);
    d = 0.0f;
    acc = make_float4(0.f, 0.f, 0.f, 0.f);
    #pragma unroll
    for (int k = 0; k < GROUP; k++) {
        float e = __expf(s[k] - m);
        d += e;
        acc.x = fmaf(e, f[k].x, acc.x);
        acc.y = fmaf(e, f[k].y, acc.y);
        acc.z = fmaf(e, f[k].z, acc.z);
        acc.w = fmaf(e, f[k].w, acc.w);
    }

    // ---- Group B: neighbors 5..9 (reuse f/s registers) ----
    #pragma unroll
    for (int k = 0; k < GROUP; k++) {
        unsigned off = __shfl_sync(0xffffffffu, mybase, GROUP + k) + (unsigned)(lane * 16);
        f[k] = ldg_nc_na((const char*)table + off);
        s[k] = f[k].x * w4.x + f[k].y * w4.y + f[k].z * w4.z + f[k].w * w4.w;
    }
    #pragma unroll
    for (int off = 16; off > 0; off >>= 1) {
        #pragma unroll
        for (int k = 0; k < GROUP; k++)
            s[k] += __shfl_xor_sync(0xffffffffu, s[k], off);
    }
    float mB = s[0];
    #pragma unroll
    for (int k = 1; k < GROUP; k++) mB = fmaxf(mB, s[k]);

    // Online-softmax rescale to the combined max.
    float newm  = fmaxf(m, mB);
    float scale = __expf(m - newm);
    d *= scale;
    acc.x *= scale; acc.y *= scale; acc.z *= scale; acc.w *= scale;

    #pragma unroll
    for (int k = 0; k < GROUP; k++) {
        float e = __expf(s[k] - newm);
        d += e;
        acc.x = fmaf(e, f[k].x, acc.x);
        acc.y = fmaf(e, f[k].y, acc.y);
        acc.z = fmaf(e, f[k].z, acc.z);
        acc.w = fmaf(e, f[k].w, acc.w);
    }

    float inv = __frcp_rn(d);
    acc.x *= inv; acc.y *= inv; acc.z *= inv; acc.w *= inv;

    // Streaming store: keep the 51MB output from evicting the table in L2.
    __stcs(&((float4*)out)[(size_t)node * 32 + lane], acc);
}

extern "C" void kernel_launch(void* const* d_in, const int* in_sizes, int n_in,
                              void* d_out, int out_size)
{
    // Identify inputs by element count:
    //   attn_w: exactly 128; table: large multiple of 128; idx: the remaining one.
    int ti = -1, wi = -1, ii = -1;
    for (int i = 0; i < n_in; i++) {
        if (in_sizes[i] == 128 && wi < 0) { wi = i; continue; }
        if (in_sizes[i] >= (1 << 20) && (in_sizes[i] % 128) == 0 && ti < 0) { ti = i; continue; }
    }
    for (int i = 0; i < n_in; i++) if (i != ti && i != wi) { ii = i; break; }

    const float* table  = (const float*)d_in[ti];
    const float* attn_w = (const float*)d_in[wi];
    const int*   nidx   = (const int*)d_in[ii];

    int n_nodes = in_sizes[ii] / K_NEIGH;
    int vocab   = in_sizes[ti] / 128;

    int blocks = (n_nodes + WARPS_PER_BLOCK - 1) / WARPS_PER_BLOCK;
    attn_agg_kernel<<<blocks, BLOCK_THREADS>>>(table, attn_w, nidx, (float*)d_out,
                                               n_nodes, vocab);
}

// round 16
// speedup vs baseline: 1.0197x; 1.0197x over previous
#include <cuda_runtime.h>

// AttentionAggregator: out[n] = sum_k softmax_k(feats[n,k]·w) * feats[n,k],
// feats[n,k] = embed_table[neigh_idx[n,k]].
// table [VOCAB,128] f32, attn_w [128] f32, neigh_idx [N,10] (int32 or int64), out [N,128] f32.
//
// R15 = R12 byte-for-byte (best measured: 51.7us). Stability re-bench after
// R14's L1::no_allocate regression (54.8us: L1 allocation captures real
// temporal reuse; bypassing it raised DRAM traffic). Config: warp-per-node,
// online softmax in 2 groups of 5 (rows register-resident, gathered once),
// butterfly score reduction, 64-thread blocks (minimal per-CTA L1tex-queue
// burst, 50 warps/SM at regs=40), no smem, no barriers, single launch,
// __stcs output to protect table L2 residency. ~97% of measured LTS ceiling.

#define K_NEIGH 10
#define GROUP 5
#define WARPS_PER_BLOCK 2
#define BLOCK_THREADS 64

__global__ __launch_bounds__(BLOCK_THREADS) void attn_agg_kernel(
    const float* __restrict__ table,
    const float* __restrict__ attn_w,
    const int*   __restrict__ idx_words,   // raw index buffer viewed as int32 words
    float* __restrict__ out,
    int n_nodes,
    int vocab)
{
    int warp = threadIdx.x >> 5;
    int lane = threadIdx.x & 31;
    int node = blockIdx.x * WARPS_PER_BLOCK + warp;
    if (node >= n_nodes) return;

    // Inline dtype detection: int64 indices in [0,2^31) have all-zero odd
    // int32 words; an int32 buffer has random vocab ids there.
    int oddw = 0;
    if (lane < 16) oddw = idx_words[2 * lane + 1];
    bool is32 = __ballot_sync(0xffffffffu, oddw != 0) != 0u;

    // Load this node's K indices (lanes 0..9) -> row byte offsets.
    unsigned mybase = 0;
    if (lane < K_NEIGH) {
        int r;
        if (is32) r = idx_words[node * K_NEIGH + lane];
        else      r = (int)((const long long*)idx_words)[(size_t)node * K_NEIGH + lane];
        r = min(max(r, 0), vocab - 1);
        mybase = (unsigned)r * 512u;          // 128 floats per row
    }

    float4 w4 = ((const float4*)attn_w)[lane];

    float4 f[GROUP];
    float  s[GROUP];
    float  m, d;
    float4 acc;

    // ---- Group A: neighbors 0..4 ----
    #pragma unroll
    for (int k = 0; k < GROUP; k++) {
        unsigned off = __shfl_sync(0xffffffffu, mybase, k) + (unsigned)(lane * 16);
        f[k] = *(const float4*)((const char*)table + off);
        s[k] = f[k].x * w4.x + f[k].y * w4.y + f[k].z * w4.z + f[k].w * w4.w;
    }
    #pragma unroll
    for (int off = 16; off > 0; off >>= 1) {
        #pragma unroll
        for (int k = 0; k < GROUP; k++)
            s[k] += __shfl_xor_sync(0xffffffffu, s[k], off);
    }
    m = s[0];
    #pragma unroll
    for (int k = 1; k < GROUP; k++) m = fmaxf(m, s[k]);
    d = 0.0f;
    acc = make_float4(0.f, 0.f, 0.f, 0.f);
    #pragma unroll
    for (int k = 0; k < GROUP; k++) {
        float e = __expf(s[k] - m);
        d += e;
        acc.x = fmaf(e, f[k].x, acc.x);
        acc.y = fmaf(e, f[k].y, acc.y);
        acc.z = fmaf(e, f[k].z, acc.z);
        acc.w = fmaf(e, f[k].w, acc.w);
    }

    // ---- Group B: neighbors 5..9 (reuse f/s registers) ----
    #pragma unroll
    for (int k = 0; k < GROUP; k++) {
        unsigned off = __shfl_sync(0xffffffffu, mybase, GROUP + k) + (unsigned)(lane * 16);
        f[k] = *(const float4*)((const char*)table + off);
        s[k] = f[k].x * w4.x + f[k].y * w4.y + f[k].z * w4.z + f[k].w * w4.w;
    }
    #pragma unroll
    for (int off = 16; off > 0; off >>= 1) {
        #pragma unroll
        for (int k = 0; k < GROUP; k++)
            s[k] += __shfl_xor_sync(0xffffffffu, s[k], off);
    }
    float mB = s[0];
    #pragma unroll
    for (int k = 1; k < GROUP; k++) mB = fmaxf(mB, s[k]);

    // Online-softmax rescale to the combined max.
    float newm  = fmaxf(m, mB);
    float scale = __expf(m - newm);
    d *= scale;
    acc.x *= scale; acc.y *= scale; acc.z *= scale; acc.w *= scale;

    #pragma unroll
    for (int k = 0; k < GROUP; k++) {
        float e = __expf(s[k] - newm);
        d += e;
        acc.x = fmaf(e, f[k].x, acc.x);
        acc.y = fmaf(e, f[k].y, acc.y);
        acc.z = fmaf(e, f[k].z, acc.z);
        acc.w = fmaf(e, f[k].w, acc.w);
    }

    float inv = __frcp_rn(d);
    acc.x *= inv; acc.y *= inv; acc.z *= inv; acc.w *= inv;

    // Streaming store: keep the 51MB output from evicting the table in L2.
    __stcs(&((float4*)out)[(size_t)node * 32 + lane], acc);
}

extern "C" void kernel_launch(void* const* d_in, const int* in_sizes, int n_in,
                              void* d_out, int out_size)
{
    // Identify inputs by element count:
    //   attn_w: exactly 128; table: large multiple of 128; idx: the remaining one.
    int ti = -1, wi = -1, ii = -1;
    for (int i = 0; i < n_in; i++) {
        if (in_sizes[i] == 128 && wi < 0) { wi = i; continue; }
        if (in_sizes[i] >= (1 << 20) && (in_sizes[i] % 128) == 0 && ti < 0) { ti = i; continue; }
    }
    for (int i = 0; i < n_in; i++) if (i != ti && i != wi) { ii = i; break; }

    const float* table  = (const float*)d_in[ti];
    const float* attn_w = (const float*)d_in[wi];
    const int*   nidx   = (const int*)d_in[ii];

    int n_nodes = in_sizes[ii] / K_NEIGH;
    int vocab   = in_sizes[ti] / 128;

    int blocks = (n_nodes + WARPS_PER_BLOCK - 1) / WARPS_PER_BLOCK;
    attn_agg_kernel<<<blocks, BLOCK_THREADS>>>(table, attn_w, nidx, (float*)d_out,
                                               n_nodes, vocab);
}